// round 16
// baseline (speedup 1.0000x reference)
#include <cuda_runtime.h>

#define FF 40
#define EE 64
#define PP 780                  // 40*39/2 pairs
#define GG 2                    // batch rows per block
#define OUTROW4 (PP * EE / 4)   // 12480 float4 per batch row
#define XROW4 (FF * EE / 4)     // 640 float4 per x row
#define THREADS 512
#define NT 9                    // row-aligned inter tiles
#define MAXTP 108               // max pairs per tile
#define WSSTRIDE (MAXTP * 16)   // float4 stride of one ws buffer

// Row-aligned tiles over all 780 pairs: counts {77,108,99,90,106,90,90,84,36}.
__constant__ int c_i0[NT + 1] = {0, 2, 5, 8, 11, 15, 19, 24, 31, 40};
__constant__ int c_pb[NT + 1] = {0, 77, 185, 284, 374, 480, 570, 660, 744, 780};

// Scratch written each launch (deterministic, allocation-free).
__device__ __align__(16) float d_inter[PP * EE];

__device__ __forceinline__ void cpa16(void* dst_smem, const void* src) {
    unsigned d = (unsigned)__cvta_generic_to_shared(dst_smem);
    asm volatile("cp.async.cg.shared.global [%0], [%1], 16;\n" :: "r"(d), "l"(src));
}
#define CPA_COMMIT() asm volatile("cp.async.commit_group;\n" ::: "memory")
#define CPA_WAIT1()  asm volatile("cp.async.wait_group 1;\n" ::: "memory")
#define CPA_WAIT0()  asm volatile("cp.async.wait_group 0;\n" ::: "memory")

__device__ __forceinline__ unsigned long long mul2(unsigned long long a,
                                                   unsigned long long b) {
    unsigned long long r;
    asm("mul.rn.f32x2 %0, %1, %2;" : "=l"(r) : "l"(a), "l"(b));
    return r;
}

// inter[p,e] = fe[i,j,e] * fe[j,i,e] in triu row-major pair order.
__global__ void ffm_init(const float* __restrict__ fe) {
    int p = blockIdx.x;
    int e = threadIdx.x;
    int i = 0, rem = p;
    while (rem >= FF - 1 - i) { rem -= FF - 1 - i; i++; }
    int j = i + 1 + rem;
    d_inter[p * EE + e] = fe[(i * FF + j) * EE + e] * fe[(j * FF + i) * EE + e];
}

// Block bx: batch rows [bx*2, bx*2+2), ALL 780 pairs via 9 double-buffered
// inter tiles (cp.async). Thread map: t = e4(16) | gq(2) | ps(16).
// Warp lanes = e4 x gq: the w (inter) LDS is identical across gq -> smem
// broadcast. a hoisted per i-row. Inner loop: 2 LDS.128 + 4 mul.f32x2 +
// 1 STG.cs.v2.b64, three running pointers (no per-iter IMAD address math).
__global__ __launch_bounds__(THREADS, 2)
void ffm_main(const float4* __restrict__ x4, float4* __restrict__ out4) {
    extern __shared__ unsigned char smem_raw[];
    float4* xs = (float4*)smem_raw;                          // 20480 B
    float4* ws = (float4*)(smem_raw + GG * XROW4 * 16);      // 2 x 27648 B

    const int t = threadIdx.x;
    const size_t b0 = (size_t)blockIdx.x * GG;

    // Stage GG x rows (cp.async, group 0).
    #pragma unroll
    for (int g = 0; g < GG; g++)
        for (int k = t; k < XROW4; k += THREADS)
            cpa16(&xs[g * XROW4 + k], &x4[(b0 + g) * XROW4 + k]);

    const float4* __restrict__ inter4 = (const float4*)d_inter;

    // Fill tile 0 (completes group 0 together with x).
    for (int k = t; k < c_pb[1] * 16; k += THREADS)
        cpa16(&ws[k], &inter4[k]);
    CPA_COMMIT();

    const int e4 = t & 15;
    const int gq = (t >> 4) & 1;
    const int ps = t >> 5;                                   // 0..15, warp-uniform

    const float4* __restrict__ xg = xs + gq * XROW4;
    float4* __restrict__ orow = out4 + (b0 + gq) * OUTROW4;

    int cur = 0;
    #pragma unroll
    for (int tile = 0; tile < NT; tile++) {
        if (tile) __syncthreads();           // everyone done with previous tile
        if (tile + 1 < NT) {                 // prefetch next tile into other buffer
            const int pb1 = c_pb[tile + 1];
            const int cnt = (c_pb[tile + 2] - pb1) * 16;
            float4* buf = ws + (cur ^ 1) * WSSTRIDE;
            for (int k = t; k < cnt; k += THREADS)
                cpa16(&buf[k], &inter4[pb1 * 16 + k]);
            CPA_COMMIT();
            CPA_WAIT1();                     // current tile's group done
        } else {
            CPA_WAIT0();
        }
        __syncthreads();

        const float4* __restrict__ wbuf = ws + cur * WSSTRIDE;
        const int pb = c_pb[tile];
        const int i1 = c_i0[tile + 1];
        int prow = 0;                        // tile-local pair index of (i, i+1)
        for (int i = c_i0[tile]; i < i1; i++) {
            const ulonglong2 a2 =
                *(const ulonglong2*)(xg + i * 16 + e4);      // one LDS per row
            const ulonglong2* bp =
                (const ulonglong2*)(xg + (i + 1 + ps) * 16 + e4);
            const ulonglong2* wp =
                (const ulonglong2*)(wbuf + (prow + ps) * 16 + e4);
            float4* op = orow + (size_t)(pb + prow + ps) * 16 + e4;
            #pragma unroll 2
            for (int j = i + 1 + ps; j < FF;
                 j += 16, bp += 256, wp += 256, op += 256) {
                const ulonglong2 b2 = *bp;
                const ulonglong2 w2 = *wp;                   // broadcast across gq
                unsigned long long r0 = mul2(mul2(a2.x, b2.x), w2.x);
                unsigned long long r1 = mul2(mul2(a2.y, b2.y), w2.y);
                asm volatile("st.global.cs.v2.b64 [%0], {%1, %2};"
                             :: "l"(op), "l"(r0), "l"(r1) : "memory");
            }
            prow += FF - 1 - i;
        }
        cur ^= 1;
    }
}

extern "C" void kernel_launch(void* const* d_in, const int* in_sizes, int n_in,
                              void* d_out, int out_size) {
    // x: 4096*40*64 = 10,485,760 elems; feat_embedding: 40*40*64 = 102,400.
    const float* x;
    const float* fe;
    if (in_sizes[0] > in_sizes[1]) {
        x  = (const float*)d_in[0];
        fe = (const float*)d_in[1];
    } else {
        x  = (const float*)d_in[1];
        fe = (const float*)d_in[0];
    }

    ffm_init<<<PP, EE>>>(fe);

    const int smem = GG * XROW4 * 16 + 2 * WSSTRIDE * 16;   // 20480 + 55296 = 75776
    cudaFuncSetAttribute(ffm_main, cudaFuncAttributeMaxDynamicSharedMemorySize, smem);
    ffm_main<<<4096 / GG, THREADS, smem>>>((const float4*)x, (float4*)d_out);
}

// round 17
// speedup vs baseline: 1.0246x; 1.0246x over previous
#include <cuda_runtime.h>

#define FF 40
#define EE 64
#define PP 780                  // 40*39/2 pairs
#define GG 2                    // batch rows per block
#define OUTROW4 (PP * EE / 4)   // 12480 float4 per batch row
#define XROW4 (FF * EE / 4)     // 640 float4 per x row
#define THREADS 512
#define NT 9                    // row-aligned inter tiles
#define MAXTP 108               // max pairs per tile
#define WSSTRIDE (MAXTP * 16)   // float4 stride of one ws buffer

// Row-aligned tiles over all 780 pairs: counts {77,108,99,90,106,90,90,84,36}.
__constant__ int c_i0[NT + 1] = {0, 2, 5, 8, 11, 15, 19, 24, 31, 40};
__constant__ int c_pb[NT + 1] = {0, 77, 185, 284, 374, 480, 570, 660, 744, 780};

// Scratch written each launch (deterministic, allocation-free).
__device__ __align__(16) float d_inter[PP * EE];

__device__ __forceinline__ void cpa16(void* dst_smem, const void* src) {
    unsigned d = (unsigned)__cvta_generic_to_shared(dst_smem);
    asm volatile("cp.async.cg.shared.global [%0], [%1], 16;\n" :: "r"(d), "l"(src));
}
#define CPA_COMMIT() asm volatile("cp.async.commit_group;\n" ::: "memory")
#define CPA_WAIT1()  asm volatile("cp.async.wait_group 1;\n" ::: "memory")
#define CPA_WAIT0()  asm volatile("cp.async.wait_group 0;\n" ::: "memory")

__device__ __forceinline__ unsigned long long mul2(unsigned long long a,
                                                   unsigned long long b) {
    unsigned long long r;
    asm("mul.rn.f32x2 %0, %1, %2;" : "=l"(r) : "l"(a), "l"(b));
    return r;
}

// inter[p,e] = fe[i,j,e] * fe[j,i,e] in triu row-major pair order.
__global__ void ffm_init(const float* __restrict__ fe) {
    int p = blockIdx.x;
    int e = threadIdx.x;
    int i = 0, rem = p;
    while (rem >= FF - 1 - i) { rem -= FF - 1 - i; i++; }
    int j = i + 1 + rem;
    d_inter[p * EE + e] = fe[(i * FF + j) * EE + e] * fe[(j * FF + i) * EE + e];
}

// Block bx: batch rows [bx*2, bx*2+2), ALL 780 pairs via 9 double-buffered
// inter tiles (cp.async). Thread map: t = e4(16) | gq(2) | ps(16).
// Warp lanes = e4 x gq: the w (inter) LDS is identical across gq -> smem
// broadcast. a hoisted per i-row. Inner loop: 2 LDS.128 + 4 mul.f32x2 +
// 1 STG.cs.v2.b64, three running pointers (no per-iter IMAD address math).
__global__ __launch_bounds__(THREADS, 2)
void ffm_main(const float4* __restrict__ x4, float4* __restrict__ out4) {
    extern __shared__ unsigned char smem_raw[];
    float4* xs = (float4*)smem_raw;                          // 20480 B
    float4* ws = (float4*)(smem_raw + GG * XROW4 * 16);      // 2 x 27648 B

    const int t = threadIdx.x;
    const size_t b0 = (size_t)blockIdx.x * GG;

    // Stage GG x rows (cp.async, group 0).
    #pragma unroll
    for (int g = 0; g < GG; g++)
        for (int k = t; k < XROW4; k += THREADS)
            cpa16(&xs[g * XROW4 + k], &x4[(b0 + g) * XROW4 + k]);

    const float4* __restrict__ inter4 = (const float4*)d_inter;

    // Fill tile 0 (completes group 0 together with x).
    for (int k = t; k < c_pb[1] * 16; k += THREADS)
        cpa16(&ws[k], &inter4[k]);
    CPA_COMMIT();

    const int e4 = t & 15;
    const int gq = (t >> 4) & 1;
    const int ps = t >> 5;                                   // 0..15, warp-uniform

    const float4* __restrict__ xg = xs + gq * XROW4;
    float4* __restrict__ orow = out4 + (b0 + gq) * OUTROW4;

    int cur = 0;
    #pragma unroll
    for (int tile = 0; tile < NT; tile++) {
        if (tile) __syncthreads();           // everyone done with previous tile
        if (tile + 1 < NT) {                 // prefetch next tile into other buffer
            const int pb1 = c_pb[tile + 1];
            const int cnt = (c_pb[tile + 2] - pb1) * 16;
            float4* buf = ws + (cur ^ 1) * WSSTRIDE;
            for (int k = t; k < cnt; k += THREADS)
                cpa16(&buf[k], &inter4[pb1 * 16 + k]);
            CPA_COMMIT();
            CPA_WAIT1();                     // current tile's group done
        } else {
            CPA_WAIT0();
        }
        __syncthreads();

        const float4* __restrict__ wbuf = ws + cur * WSSTRIDE;
        const int pb = c_pb[tile];
        const int i1 = c_i0[tile + 1];
        int prow = 0;                        // tile-local pair index of (i, i+1)
        for (int i = c_i0[tile]; i < i1; i++) {
            const ulonglong2 a2 =
                *(const ulonglong2*)(xg + i * 16 + e4);      // one LDS per row
            const ulonglong2* bp =
                (const ulonglong2*)(xg + (i + 1 + ps) * 16 + e4);
            const ulonglong2* wp =
                (const ulonglong2*)(wbuf + (prow + ps) * 16 + e4);
            float4* op = orow + (size_t)(pb + prow + ps) * 16 + e4;
            #pragma unroll 2
            for (int j = i + 1 + ps; j < FF;
                 j += 16, bp += 256, wp += 256, op += 256) {
                const ulonglong2 b2 = *bp;
                const ulonglong2 w2 = *wp;                   // broadcast across gq
                unsigned long long r0 = mul2(mul2(a2.x, b2.x), w2.x);
                unsigned long long r1 = mul2(mul2(a2.y, b2.y), w2.y);
                asm volatile("st.global.cs.v2.b64 [%0], {%1, %2};"
                             :: "l"(op), "l"(r0), "l"(r1) : "memory");
            }
            prow += FF - 1 - i;
        }
        cur ^= 1;
    }
}

extern "C" void kernel_launch(void* const* d_in, const int* in_sizes, int n_in,
                              void* d_out, int out_size) {
    // x: 4096*40*64 = 10,485,760 elems; feat_embedding: 40*40*64 = 102,400.
    const float* x;
    const float* fe;
    if (in_sizes[0] > in_sizes[1]) {
        x  = (const float*)d_in[0];
        fe = (const float*)d_in[1];
    } else {
        x  = (const float*)d_in[1];
        fe = (const float*)d_in[0];
    }

    ffm_init<<<PP, EE>>>(fe);

    const int smem = GG * XROW4 * 16 + 2 * WSSTRIDE * 16;   // 20480 + 55296 = 75776
    cudaFuncSetAttribute(ffm_main, cudaFuncAttributeMaxDynamicSharedMemorySize, smem);
    ffm_main<<<4096 / GG, THREADS, smem>>>((const float4*)x, (float4*)d_out);
}